// round 1
// baseline (speedup 1.0000x reference)
#include <cuda_runtime.h>
#include <cuda_bf16.h>
#include <math.h>

#define NN 50000
#define EE 1600000
#define D  128       // H*C
#define CH 32
#define NH 4

// ---------------- scratch (device globals; no allocation allowed) ----------------
__device__ float g_xl[NN * D];
__device__ float g_xr[NN * D];
__device__ float g_h [NN * D];
__device__ int   g_rowptr[NN + 1];
__device__ int   g_cur[NN];          // counts, then scatter cursors
__device__ int   g_src_sorted[EE];
__device__ float g_ew_sorted [EE];
__device__ float g_partials[1024];
__device__ float g_mean;

// ---------------- mean edge weight (deterministic 2-stage) ----------------
__global__ void k_mean_partial(const float* __restrict__ ew) {
    __shared__ float s[256];
    float sum = 0.f;
    for (int i = blockIdx.x * 256 + threadIdx.x; i < EE; i += 1024 * 256)
        sum += ew[i];
    s[threadIdx.x] = sum; __syncthreads();
    for (int o = 128; o > 0; o >>= 1) {
        if (threadIdx.x < o) s[threadIdx.x] += s[threadIdx.x + o];
        __syncthreads();
    }
    if (threadIdx.x == 0) g_partials[blockIdx.x] = s[0];
}

__global__ void k_mean_final() {
    __shared__ float s[1024];
    s[threadIdx.x] = g_partials[threadIdx.x]; __syncthreads();
    for (int o = 512; o > 0; o >>= 1) {
        if (threadIdx.x < o) s[threadIdx.x] += s[threadIdx.x + o];
        __syncthreads();
    }
    if (threadIdx.x == 0) g_mean = s[0] / (float)EE;
}

// ---------------- CSR build by dst ----------------
__global__ void k_zero_counts() {
    int i = blockIdx.x * 256 + threadIdx.x;
    if (i < NN) g_cur[i] = 0;
}

__global__ void k_hist(const int* __restrict__ dst) {
    int e = blockIdx.x * 256 + threadIdx.x;
    if (e < EE) atomicAdd(&g_cur[dst[e]], 1);
}

__global__ void k_scan() {   // single block, 1024 threads; exclusive scan of counts
    __shared__ int s[1024];
    int tid = threadIdx.x;
    int carry = 0;
    for (int base = 0; base < NN; base += 1024) {
        int i = base + tid;
        int v = (i < NN) ? g_cur[i] : 0;
        s[tid] = v; __syncthreads();
        for (int o = 1; o < 1024; o <<= 1) {
            int t = (tid >= o) ? s[tid - o] : 0;
            __syncthreads();
            s[tid] += t;
            __syncthreads();
        }
        int incl  = s[tid];
        int total = s[1023];
        __syncthreads();
        int excl = incl - v + carry;
        if (i < NN) { g_rowptr[i] = excl; g_cur[i] = excl; }
        carry += total;
        __syncthreads();
    }
    if (tid == 0) g_rowptr[NN] = carry;   // == EE
}

__global__ void k_scatter(const int* __restrict__ src, const int* __restrict__ dst,
                          const float* __restrict__ ew) {
    int e = blockIdx.x * 256 + threadIdx.x;
    if (e < EE) {
        int d   = dst[e];
        int pos = atomicAdd(&g_cur[d], 1);
        g_src_sorted[pos] = src[e];
        g_ew_sorted [pos] = ew[e];
    }
}

// ---------------- SGEMM: C[nrows x 128] = A[nrows x 128] * B[128 x 128] ----------------
__global__ __launch_bounds__(256) void k_gemm(const float* __restrict__ A,
                                              const float* __restrict__ B,
                                              float* __restrict__ C, int nrows) {
    const int BM = 128, BK = 16;
    __shared__ float As[BK][BM];
    __shared__ float Bs[BK][128];
    int tid = threadIdx.x;                 // 256
    int block_row = blockIdx.x * BM;
    int tcol = tid & 15;                   // 16 col groups x 8
    int trow = tid >> 4;                   // 16 row groups x 8
    float acc[8][8];
    #pragma unroll
    for (int i = 0; i < 8; i++)
        #pragma unroll
        for (int j = 0; j < 8; j++) acc[i][j] = 0.f;

    for (int k0 = 0; k0 < 128; k0 += BK) {
        // load A tile (128x16) transposed into As[BK][BM]
        #pragma unroll
        for (int l = 0; l < 2; l++) {
            int idx = tid + l * 256;        // 0..511 float4s
            int ar  = idx >> 2;
            int ac4 = idx & 3;
            int grow = block_row + ar;
            float4 v = make_float4(0.f, 0.f, 0.f, 0.f);
            if (grow < nrows) v = *(const float4*)&A[grow * 128 + k0 + ac4 * 4];
            As[ac4 * 4 + 0][ar] = v.x;
            As[ac4 * 4 + 1][ar] = v.y;
            As[ac4 * 4 + 2][ar] = v.z;
            As[ac4 * 4 + 3][ar] = v.w;
        }
        // load B tile (16x128)
        #pragma unroll
        for (int l = 0; l < 2; l++) {
            int idx = tid + l * 256;
            int br  = idx >> 5;             // k row 0..15
            int bc4 = idx & 31;
            *(float4*)&Bs[br][bc4 * 4] = *(const float4*)&B[(k0 + br) * 128 + bc4 * 4];
        }
        __syncthreads();
        #pragma unroll
        for (int k = 0; k < BK; k++) {
            float a[8], b[8];
            #pragma unroll
            for (int i = 0; i < 8; i++) a[i] = As[k][trow * 8 + i];
            #pragma unroll
            for (int j = 0; j < 8; j++) b[j] = Bs[k][tcol * 8 + j];
            #pragma unroll
            for (int i = 0; i < 8; i++)
                #pragma unroll
                for (int j = 0; j < 8; j++)
                    acc[i][j] = fmaf(a[i], b[j], acc[i][j]);
        }
        __syncthreads();
    }
    #pragma unroll
    for (int i = 0; i < 8; i++) {
        int grow = block_row + trow * 8 + i;
        if (grow < nrows) {
            #pragma unroll
            for (int j4 = 0; j4 < 2; j4++) {
                float4 v = make_float4(acc[i][j4*4+0], acc[i][j4*4+1],
                                       acc[i][j4*4+2], acc[i][j4*4+3]);
                *(float4*)&C[grow * 128 + tcol * 8 + j4 * 4] = v;
            }
        }
    }
}

// ---------------- fused per-dst GATv2 edge pass with online softmax ----------------
// block = dst node (128 threads); warp = head; lane = channel
template <bool CONCAT>
__global__ __launch_bounds__(128) void k_edge(const float* __restrict__ xl,
                                              const float* __restrict__ xr,
                                              const float* __restrict__ We,
                                              const float* __restrict__ att,
                                              const float* __restrict__ bias,
                                              float* __restrict__ out) {
    int d   = blockIdx.x;
    int tid = threadIdx.x;               // 0..127 ; h = tid>>5, c = tid&31
    float xr_d = xr[d * D + tid];
    float we   = __ldg(&We[tid]);
    float at   = __ldg(&att[tid]);
    float mean = g_mean;

    // self-loop seeds the online softmax (every node has exactly one)
    float xl_self = xl[d * D + tid];
    float z = xl_self + xr_d + mean * we;
    z = (z > 0.f) ? z : 0.2f * z;
    float l = z * at;
    #pragma unroll
    for (int o = 16; o > 0; o >>= 1) l += __shfl_xor_sync(0xffffffffu, l, o);

    float m = l;          // running max (lane-uniform per warp)
    float denom = 1.0f;   // exp(l_self - m) = 1
    float acc = xl_self;  // 1 * xl_self

    int beg = g_rowptr[d], end = g_rowptr[d + 1];
    // software-pipelined edge loop
    int   s_next = 0; float w_next = 0.f, xls_next = 0.f;
    if (beg < end) {
        s_next   = g_src_sorted[beg];
        w_next   = g_ew_sorted [beg];
        xls_next = xl[s_next * D + tid];
    }
    for (int i = beg; i < end; i++) {
        float xls = xls_next;
        float w   = w_next;
        int j = i + 1;
        if (j < end) {
            s_next   = g_src_sorted[j];
            w_next   = g_ew_sorted [j];
            xls_next = xl[s_next * D + tid];
        }
        float zz = xls + xr_d + w * we;
        zz = (zz > 0.f) ? zz : 0.2f * zz;
        float le = zz * at;
        #pragma unroll
        for (int o = 16; o > 0; o >>= 1) le += __shfl_xor_sync(0xffffffffu, le, o);
        if (le <= m) {                    // warp-uniform branch (le, m lane-uniform)
            float p = __expf(le - m);
            denom += p;
            acc = fmaf(p, xls, acc);
        } else {
            float r = __expf(m - le);
            denom = fmaf(denom, r, 1.0f);
            acc   = fmaf(acc,   r, xls);
            m = le;
        }
    }

    float o = acc / (denom + 1e-16f);
    if (CONCAT) {
        float v = o + __ldg(&bias[tid]);
        v = (v > 0.f) ? v : expm1f(v);    // ELU
        out[d * D + tid] = v;
    } else {
        __shared__ float sb[D];
        sb[tid] = o;
        __syncthreads();
        if (tid < CH) {
            float v = (sb[tid] + sb[tid + 32] + sb[tid + 64] + sb[tid + 96]) * 0.25f
                      + __ldg(&bias[tid]);
            out[d * CH + tid] = v;
        }
    }
}

// ---------------- launch ----------------
static float* symaddr_f(const void* sym) {
    void* p = nullptr;
    cudaGetSymbolAddress(&p, sym);
    return (float*)p;
}

extern "C" void kernel_launch(void* const* d_in, const int* in_sizes, int n_in,
                              void* d_out, int out_size) {
    const float* x    = (const float*)d_in[0];
    const int*   ei   = (const int*)  d_in[1];
    const float* ew   = (const float*)d_in[2];
    const float* Wl1  = (const float*)d_in[3];
    const float* Wr1  = (const float*)d_in[4];
    const float* We1  = (const float*)d_in[5];
    const float* att1 = (const float*)d_in[6];
    const float* b1   = (const float*)d_in[7];
    const float* Wl2  = (const float*)d_in[8];
    const float* Wr2  = (const float*)d_in[9];
    const float* We2  = (const float*)d_in[10];
    const float* att2 = (const float*)d_in[11];
    const float* b2   = (const float*)d_in[12];
    float* out = (float*)d_out;

    const int* src = ei;
    const int* dst = ei + EE;

    float* xl = symaddr_f(g_xl);
    float* xr = symaddr_f(g_xr);
    float* h  = symaddr_f(g_h);

    // mean edge weight
    k_mean_partial<<<1024, 256>>>(ew);
    k_mean_final<<<1, 1024>>>();

    // CSR by dst
    k_zero_counts<<<(NN + 255) / 256, 256>>>();
    k_hist<<<(EE + 255) / 256, 256>>>(dst);
    k_scan<<<1, 1024>>>();
    k_scatter<<<(EE + 255) / 256, 256>>>(src, dst, ew);

    const int gemm_grid = (NN + 127) / 128;

    // layer 1
    k_gemm<<<gemm_grid, 256>>>(x, Wl1, xl, NN);
    k_gemm<<<gemm_grid, 256>>>(x, Wr1, xr, NN);
    k_edge<true><<<NN, 128>>>(xl, xr, We1, att1, b1, h);

    // layer 2
    k_gemm<<<gemm_grid, 256>>>(h, Wl2, xl, NN);
    k_gemm<<<gemm_grid, 256>>>(h, Wr2, xr, NN);
    k_edge<false><<<NN, 128>>>(xl, xr, We2, att2, b2, out);
}

// round 6
// speedup vs baseline: 1.9182x; 1.9182x over previous
#include <cuda_runtime.h>
#include <cuda_bf16.h>
#include <math.h>

#define NN 50000
#define EE 1600000
#define D  128       // H*C
#define CH 32
#define NH 4
#define SCAN_BLOCKS 196   // ceil(NN/256)

// ---------------- scratch (device globals; no allocation allowed) ----------------
__device__ float g_xl[NN * D];
__device__ float g_xr[NN * D];
__device__ float g_h [NN * D];
__device__ int   g_rowptr[NN + 1];
__device__ int   g_cur[NN];          // counts, then scatter cursors
__device__ int2  g_edge[EE];         // (src, bitcast(ew)) sorted by dst
__device__ int   g_blocksums[256];
__device__ float g_partials[1024];
__device__ float g_mean;

// ---------------- mean edge weight (deterministic 2-stage) ----------------
__global__ void k_mean_partial(const float* __restrict__ ew) {
    __shared__ float s[256];
    float sum = 0.f;
    for (int i = blockIdx.x * 256 + threadIdx.x; i < EE; i += 1024 * 256)
        sum += ew[i];
    s[threadIdx.x] = sum; __syncthreads();
    for (int o = 128; o > 0; o >>= 1) {
        if (threadIdx.x < o) s[threadIdx.x] += s[threadIdx.x + o];
        __syncthreads();
    }
    if (threadIdx.x == 0) g_partials[blockIdx.x] = s[0];
}

__global__ void k_mean_final() {
    __shared__ float s[1024];
    s[threadIdx.x] = g_partials[threadIdx.x]; __syncthreads();
    for (int o = 512; o > 0; o >>= 1) {
        if (threadIdx.x < o) s[threadIdx.x] += s[threadIdx.x + o];
        __syncthreads();
    }
    if (threadIdx.x == 0) g_mean = s[0] / (float)EE;
}

// ---------------- CSR build by dst ----------------
__global__ void k_zero_counts() {
    int i = blockIdx.x * 256 + threadIdx.x;
    if (i < NN) g_cur[i] = 0;
}

__global__ void k_hist(const int* __restrict__ dst) {
    int e = blockIdx.x * 256 + threadIdx.x;
    if (e < EE) atomicAdd(&g_cur[dst[e]], 1);
}

// multi-block scan, 3 kernels
__global__ void k_scan1() {
    __shared__ int s[256];
    int tid = threadIdx.x;
    int i = blockIdx.x * 256 + tid;
    int v = (i < NN) ? g_cur[i] : 0;
    s[tid] = v; __syncthreads();
    for (int o = 1; o < 256; o <<= 1) {
        int t = (tid >= o) ? s[tid - o] : 0;
        __syncthreads();
        s[tid] += t;
        __syncthreads();
    }
    if (i < NN) g_rowptr[i] = s[tid];               // block-local inclusive (temp)
    if (tid == 255) g_blocksums[blockIdx.x] = s[255];
}

__global__ void k_scan2() {   // single block: exclusive scan of block sums
    __shared__ int s[256];
    int tid = threadIdx.x;
    int v = (tid < SCAN_BLOCKS) ? g_blocksums[tid] : 0;
    s[tid] = v; __syncthreads();
    for (int o = 1; o < 256; o <<= 1) {
        int t = (tid >= o) ? s[tid - o] : 0;
        __syncthreads();
        s[tid] += t;
        __syncthreads();
    }
    g_blocksums[tid] = s[tid] - v;   // exclusive
}

__global__ void k_scan3() {
    int i = blockIdx.x * 256 + threadIdx.x;
    if (i < NN) {
        int excl = g_rowptr[i] - g_cur[i] + g_blocksums[blockIdx.x];
        g_rowptr[i] = excl;
        g_cur[i]    = excl;
    }
    if (blockIdx.x == 0 && threadIdx.x == 0) g_rowptr[NN] = EE;
}

__global__ void k_scatter(const int* __restrict__ src, const int* __restrict__ dst,
                          const float* __restrict__ ew) {
    int e = blockIdx.x * 256 + threadIdx.x;
    if (e < EE) {
        int d   = dst[e];
        int pos = atomicAdd(&g_cur[d], 1);
        g_edge[pos] = make_int2(src[e], __float_as_int(ew[e]));
    }
}

// ---------------- SGEMM via packed f32x2 FFMA ----------------
// C[nrows x 128] = A[nrows x 128] * B[128 x 128]; two (B,C) pairs via blockIdx.y
__global__ __launch_bounds__(256) void k_gemm2(const float* __restrict__ A,
                                               const float* __restrict__ B0,
                                               float* __restrict__ C0,
                                               const float* __restrict__ B1,
                                               float* __restrict__ C1,
                                               int nrows) {
    const float* __restrict__ B = blockIdx.y ? B1 : B0;
    float* __restrict__ C = blockIdx.y ? C1 : C0;
    const int BM = 128, BK = 16;
    __shared__ float As[BK][BM];
    __shared__ float Bs[BK][128];
    int tid = threadIdx.x;                 // 256
    int block_row = blockIdx.x * BM;
    int tcol = tid & 15;                   // 16 col groups
    int trow = tid >> 4;                   // 16 row groups x 8
    // thread's columns: [tcol*4 .. tcol*4+3] and [64+tcol*4 .. 64+tcol*4+3]
    unsigned long long acc2[8][4];
    #pragma unroll
    for (int i = 0; i < 8; i++)
        #pragma unroll
        for (int j = 0; j < 4; j++) acc2[i][j] = 0ULL;

    for (int k0 = 0; k0 < 128; k0 += BK) {
        #pragma unroll
        for (int l = 0; l < 2; l++) {
            int idx = tid + l * 256;        // 0..511 float4s
            int ar  = idx >> 2;
            int ac4 = idx & 3;
            int grow = block_row + ar;
            float4 v = make_float4(0.f, 0.f, 0.f, 0.f);
            if (grow < nrows) v = *(const float4*)&A[grow * 128 + k0 + ac4 * 4];
            As[ac4 * 4 + 0][ar] = v.x;
            As[ac4 * 4 + 1][ar] = v.y;
            As[ac4 * 4 + 2][ar] = v.z;
            As[ac4 * 4 + 3][ar] = v.w;
        }
        #pragma unroll
        for (int l = 0; l < 2; l++) {
            int idx = tid + l * 256;
            int br  = idx >> 5;
            int bc4 = idx & 31;
            *(float4*)&Bs[br][bc4 * 4] = *(const float4*)&B[(k0 + br) * 128 + bc4 * 4];
        }
        __syncthreads();
        #pragma unroll
        for (int k = 0; k < BK; k++) {
            float a[8];
            *(float4*)&a[0] = *(const float4*)&As[k][trow * 8];
            *(float4*)&a[4] = *(const float4*)&As[k][trow * 8 + 4];
            unsigned long long b2[4];
            b2[0] = *(const unsigned long long*)&Bs[k][tcol * 4 + 0];
            b2[1] = *(const unsigned long long*)&Bs[k][tcol * 4 + 2];
            b2[2] = *(const unsigned long long*)&Bs[k][64 + tcol * 4 + 0];
            b2[3] = *(const unsigned long long*)&Bs[k][64 + tcol * 4 + 2];
            #pragma unroll
            for (int i = 0; i < 8; i++) {
                unsigned long long a2;
                asm("mov.b64 %0, {%1, %1};" : "=l"(a2) : "f"(a[i]));
                #pragma unroll
                for (int j = 0; j < 4; j++)
                    asm("fma.rn.f32x2 %0, %1, %2, %0;"
                        : "+l"(acc2[i][j]) : "l"(a2), "l"(b2[j]));
            }
        }
        __syncthreads();
    }
    #pragma unroll
    for (int i = 0; i < 8; i++) {
        int grow = block_row + trow * 8 + i;
        if (grow < nrows) {
            float4 v0, v1;
            asm("mov.b64 {%0,%1}, %2;" : "=f"(v0.x), "=f"(v0.y) : "l"(acc2[i][0]));
            asm("mov.b64 {%0,%1}, %2;" : "=f"(v0.z), "=f"(v0.w) : "l"(acc2[i][1]));
            asm("mov.b64 {%0,%1}, %2;" : "=f"(v1.x), "=f"(v1.y) : "l"(acc2[i][2]));
            asm("mov.b64 {%0,%1}, %2;" : "=f"(v1.z), "=f"(v1.w) : "l"(acc2[i][3]));
            *(float4*)&C[grow * 128 + tcol * 4]      = v0;
            *(float4*)&C[grow * 128 + 64 + tcol * 4] = v1;
        }
    }
}

// ---------------- fused per-dst GATv2 edge pass (warp per node) ----------------
// lane holds channels 4*lane..4*lane+3 (head = lane>>3); per-head reduce = 3 shfl
__device__ __forceinline__ float edge_logit(float4 xs, float4 xr4, float4 we4,
                                            float4 at4, float w) {
    float z, p;
    z = fmaf(w, we4.x, xr4.x) + xs.x; z = fmaxf(z, 0.2f * z); p = z * at4.x;
    z = fmaf(w, we4.y, xr4.y) + xs.y; z = fmaxf(z, 0.2f * z); p = fmaf(z, at4.y, p);
    z = fmaf(w, we4.z, xr4.z) + xs.z; z = fmaxf(z, 0.2f * z); p = fmaf(z, at4.z, p);
    z = fmaf(w, we4.w, xr4.w) + xs.w; z = fmaxf(z, 0.2f * z); p = fmaf(z, at4.w, p);
    p += __shfl_xor_sync(0xffffffffu, p, 1);
    p += __shfl_xor_sync(0xffffffffu, p, 2);
    p += __shfl_xor_sync(0xffffffffu, p, 4);
    return p;   // uniform within each 8-lane (per-head) group
}

template <bool CONCAT>
__global__ __launch_bounds__(256) void k_edge(const float* __restrict__ xl,
                                              const float* __restrict__ xr,
                                              const float* __restrict__ We,
                                              const float* __restrict__ att,
                                              const float* __restrict__ bias,
                                              float* __restrict__ out) {
    int d = (blockIdx.x * 256 + threadIdx.x) >> 5;
    if (d >= NN) return;
    int lane = threadIdx.x & 31;

    float mean = g_mean;
    const float4 xr4 = *(const float4*)&xr[d * D + lane * 4];
    const float4 we4 = __ldg((const float4*)&We[lane * 4]);
    const float4 at4 = __ldg((const float4*)&att[lane * 4]);

    // self-loop seeds the online softmax
    float4 xs = *(const float4*)&xl[d * D + lane * 4];
    float m = edge_logit(xs, xr4, we4, at4, mean);
    float denom = 1.0f;
    float4 acc = xs;

    int beg = g_rowptr[d], end = g_rowptr[d + 1];
    int n = end - beg;
    int2 e0, e1; float4 x0, x1;
    e0 = e1 = make_int2(0, 0);
    x0 = x1 = make_float4(0.f, 0.f, 0.f, 0.f);
    if (n > 0) { e0 = g_edge[beg];     x0 = *(const float4*)&xl[e0.x * D + lane * 4]; }
    if (n > 1) { e1 = g_edge[beg + 1]; x1 = *(const float4*)&xl[e1.x * D + lane * 4]; }

    for (int i = beg; i < end; i++) {
        float  w  = __int_as_float(e0.y);
        float4 xc = x0;
        e0 = e1; x0 = x1;
        int j = i + 2;
        if (j < end) { e1 = g_edge[j]; x1 = *(const float4*)&xl[e1.x * D + lane * 4]; }

        float le = edge_logit(xc, xr4, we4, at4, w);
        float newm = fmaxf(m, le);
        float p = __expf(le - newm);
        float r = __expf(m  - newm);
        denom = fmaf(denom, r, p);
        acc.x = fmaf(acc.x, r, p * xc.x);
        acc.y = fmaf(acc.y, r, p * xc.y);
        acc.z = fmaf(acc.z, r, p * xc.z);
        acc.w = fmaf(acc.w, r, p * xc.w);
        m = newm;
    }

    float inv = 1.0f / (denom + 1e-16f);
    float4 o = make_float4(acc.x * inv, acc.y * inv, acc.z * inv, acc.w * inv);

    if (CONCAT) {
        const float4 b4 = __ldg((const float4*)&bias[lane * 4]);
        float4 v;
        v.x = o.x + b4.x; v.x = (v.x > 0.f) ? v.x : expm1f(v.x);
        v.y = o.y + b4.y; v.y = (v.y > 0.f) ? v.y : expm1f(v.y);
        v.z = o.z + b4.z; v.z = (v.z > 0.f) ? v.z : expm1f(v.z);
        v.w = o.w + b4.w; v.w = (v.w > 0.f) ? v.w : expm1f(v.w);
        *(float4*)&out[d * D + lane * 4] = v;
    } else {
        // mean over heads: lanes l, l^8, l^16, l^24 hold same within-head channel
        float s0 = o.x, s1 = o.y, s2 = o.z, s3 = o.w;
        s0 += __shfl_xor_sync(0xffffffffu, s0, 8);
        s1 += __shfl_xor_sync(0xffffffffu, s1, 8);
        s2 += __shfl_xor_sync(0xffffffffu, s2, 8);
        s3 += __shfl_xor_sync(0xffffffffu, s3, 8);
        s0 += __shfl_xor_sync(0xffffffffu, s0, 16);
        s1 += __shfl_xor_sync(0xffffffffu, s1, 16);
        s2 += __shfl_xor_sync(0xffffffffu, s2, 16);
        s3 += __shfl_xor_sync(0xffffffffu, s3, 16);
        if (lane < 8) {
            const float4 b4 = __ldg((const float4*)&bias[lane * 4]);
            float4 r;
            r.x = s0 * 0.25f + b4.x;
            r.y = s1 * 0.25f + b4.y;
            r.z = s2 * 0.25f + b4.z;
            r.w = s3 * 0.25f + b4.w;
            *(float4*)&out[d * CH + lane * 4] = r;
        }
    }
}

// ---------------- launch ----------------
static float* symaddr_f(const void* sym) {
    void* p = nullptr;
    cudaGetSymbolAddress(&p, sym);
    return (float*)p;
}

extern "C" void kernel_launch(void* const* d_in, const int* in_sizes, int n_in,
                              void* d_out, int out_size) {
    const float* x    = (const float*)d_in[0];
    const int*   ei   = (const int*)  d_in[1];
    const float* ew   = (const float*)d_in[2];
    const float* Wl1  = (const float*)d_in[3];
    const float* Wr1  = (const float*)d_in[4];
    const float* We1  = (const float*)d_in[5];
    const float* att1 = (const float*)d_in[6];
    const float* b1   = (const float*)d_in[7];
    const float* Wl2  = (const float*)d_in[8];
    const float* Wr2  = (const float*)d_in[9];
    const float* We2  = (const float*)d_in[10];
    const float* att2 = (const float*)d_in[11];
    const float* b2   = (const float*)d_in[12];
    float* out = (float*)d_out;

    const int* src = ei;
    const int* dst = ei + EE;

    float* xl = symaddr_f(g_xl);
    float* xr = symaddr_f(g_xr);
    float* h  = symaddr_f(g_h);

    // mean edge weight
    k_mean_partial<<<1024, 256>>>(ew);
    k_mean_final<<<1, 1024>>>();

    // CSR by dst
    k_zero_counts<<<SCAN_BLOCKS, 256>>>();
    k_hist<<<(EE + 255) / 256, 256>>>(dst);
    k_scan1<<<SCAN_BLOCKS, 256>>>();
    k_scan2<<<1, 256>>>();
    k_scan3<<<SCAN_BLOCKS, 256>>>();
    k_scatter<<<(EE + 255) / 256, 256>>>(src, dst, ew);

    const dim3 gemm_grid((NN + 127) / 128, 2);
    const int  edge_grid = (NN + 7) / 8;

    // layer 1
    k_gemm2<<<gemm_grid, 256>>>(x, Wl1, xl, Wr1, xr, NN);
    k_edge<true><<<edge_grid, 256>>>(xl, xr, We1, att1, b1, h);

    // layer 2
    k_gemm2<<<gemm_grid, 256>>>(h, Wl2, xl, Wr2, xr, NN);
    k_edge<false><<<edge_grid, 256>>>(xl, xr, We2, att2, b2, out);
}